// round 4
// baseline (speedup 1.0000x reference)
#include <cuda_runtime.h>

// RNNBlock: h_t = tanh(x_t @ Wx[t] + h_{t-1} @ Wh[t]),  h_{-1} = 0
// B=512, S=512, D_IN=D_OUT=256, fp32 in/out.
//
// Decomposition:
//   K1 (parallel):  out[b,t,:] = x[b,t,:] @ Wx[t]          (Z stored in d_out)
//   K2 (recurrent): per-CTA batch slice, loop t:
//                   out[b,t,:] = tanh(out[b,t,:] + h @ Wh[t]); h = out[b,t,:]
// No inter-CTA sync anywhere; Z lives in d_out (read-then-overwrite in place).
// Compute: mma.sync m16n8k8 tf32 (fp32 accumulate), inputs cvt.rna.tf32.

#define S_LEN 512
#define B_SZ  512
#define DIM   256
#define TM    32          // batch rows per CTA tile
#define SSTRIDE 260       // smem row stride (== 4 mod 32 -> conflict-free A frags)

__device__ __forceinline__ unsigned f2tf32(float f) {
    unsigned u;
    asm("cvt.rna.tf32.f32 %0, %1;" : "=r"(u) : "f"(f));
    return u;
}

__device__ __forceinline__ void mma_tf32(float c[4],
                                         unsigned a0, unsigned a1, unsigned a2, unsigned a3,
                                         unsigned b0, unsigned b1) {
    asm volatile(
        "mma.sync.aligned.m16n8k8.row.col.f32.tf32.tf32.f32 "
        "{%0,%1,%2,%3}, {%4,%5,%6,%7}, {%8,%9}, {%0,%1,%2,%3};"
        : "+f"(c[0]), "+f"(c[1]), "+f"(c[2]), "+f"(c[3])
        : "r"(a0), "r"(a1), "r"(a2), "r"(a3), "r"(b0), "r"(b1));
}

// acc[2][4][4] += Asm(32 x 256, row stride SSTRIDE) @ Bg(256x256 row-major [k][n])
// warp covers output cols [nbase, nbase+32). B-frags loaded straight from global
// (each element read exactly once per CTA; L2-cached across CTAs).
__device__ __forceinline__ void gemm_tile(const float* __restrict__ Asm,
                                          const float* __restrict__ Bg,
                                          float acc[2][4][4],
                                          int nbase, int g, int tig) {
#pragma unroll 4
    for (int k0 = 0; k0 < DIM; k0 += 8) {
        unsigned a[2][4];
#pragma unroll
        for (int mi = 0; mi < 2; mi++) {
            int r0 = mi * 16 + g;
            a[mi][0] = f2tf32(Asm[r0 * SSTRIDE + k0 + tig]);
            a[mi][1] = f2tf32(Asm[(r0 + 8) * SSTRIDE + k0 + tig]);
            a[mi][2] = f2tf32(Asm[r0 * SSTRIDE + k0 + tig + 4]);
            a[mi][3] = f2tf32(Asm[(r0 + 8) * SSTRIDE + k0 + tig + 4]);
        }
#pragma unroll
        for (int nt = 0; nt < 4; nt++) {
            int n = nbase + nt * 8 + g;
            unsigned b0 = f2tf32(Bg[(k0 + tig) * DIM + n]);
            unsigned b1 = f2tf32(Bg[(k0 + tig + 4) * DIM + n]);
            mma_tf32(acc[0][nt], a[0][0], a[0][1], a[0][2], a[0][3], b0, b1);
            mma_tf32(acc[1][nt], a[1][0], a[1][1], a[1][2], a[1][3], b0, b1);
        }
    }
}

// ---------------- K1: Z = x @ Wx  (fully parallel over (b-tile, t)) ----------------
__global__ void __launch_bounds__(256)
rnn_k1_xwx(const float* __restrict__ x, const float* __restrict__ Wx,
           float* __restrict__ out) {
    __shared__ float xs[TM * SSTRIDE];
    const int bt  = blockIdx.x;          // 0..15  batch tile
    const int t   = blockIdx.y;          // 0..511 timestep
    const int tid = threadIdx.x;
    const int w = tid >> 5, lane = tid & 31, g = lane >> 2, tig = lane & 3;
    const int b0r = bt * TM;

    // stage x tile [32 x 256] into padded smem (float4, fully coalesced)
    for (int i = tid; i < TM * (DIM / 4); i += 256) {
        int r = i >> 6, c4 = i & 63;
        float4 v = *reinterpret_cast<const float4*>(
            x + ((size_t)(b0r + r) * S_LEN + t) * DIM + c4 * 4);
        *reinterpret_cast<float4*>(&xs[r * SSTRIDE + c4 * 4]) = v;
    }
    __syncthreads();

    float acc[2][4][4] = {};
    gemm_tile(xs, Wx + (size_t)t * DIM * DIM, acc, w * 32, g, tig);

#pragma unroll
    for (int mi = 0; mi < 2; mi++)
#pragma unroll
        for (int half = 0; half < 2; half++) {
            int r = b0r + mi * 16 + g + half * 8;
            size_t base = ((size_t)r * S_LEN + t) * DIM;
#pragma unroll
            for (int nt = 0; nt < 4; nt++) {
                int c = w * 32 + nt * 8 + tig * 2;
                *reinterpret_cast<float2*>(out + base + c) =
                    make_float2(acc[mi][nt][half * 2], acc[mi][nt][half * 2 + 1]);
            }
        }
}

// ---------------- K2: recurrence, batch-parallel (16 independent CTAs) -------------
__global__ void __launch_bounds__(256)
rnn_k2_recur(const float* __restrict__ Wh, float* __restrict__ out) {
    __shared__ float hs[TM * SSTRIDE];   // h_{t-1} for this CTA's 32 rows (fp32)
    const int tid = threadIdx.x;
    const int w = tid >> 5, lane = tid & 31, g = lane >> 2, tig = lane & 3;
    const int b0r = blockIdx.x * TM;

    for (int i = tid; i < TM * SSTRIDE; i += 256) hs[i] = 0.0f;   // h_{-1} = 0
    __syncthreads();

    for (int t = 0; t < S_LEN; t++) {
        float acc[2][4][4];
        // acc = Z (already sitting in out)
#pragma unroll
        for (int mi = 0; mi < 2; mi++)
#pragma unroll
            for (int half = 0; half < 2; half++) {
                int r = b0r + mi * 16 + g + half * 8;
                size_t base = ((size_t)r * S_LEN + t) * DIM;
#pragma unroll
                for (int nt = 0; nt < 4; nt++) {
                    int c = w * 32 + nt * 8 + tig * 2;
                    float2 v = *reinterpret_cast<const float2*>(out + base + c);
                    acc[mi][nt][half * 2]     = v.x;
                    acc[mi][nt][half * 2 + 1] = v.y;
                }
            }

        gemm_tile(hs, Wh + (size_t)t * DIM * DIM, acc, w * 32, g, tig);

        __syncthreads();   // everyone done READING hs for step t

#pragma unroll
        for (int mi = 0; mi < 2; mi++)
#pragma unroll
            for (int half = 0; half < 2; half++) {
                int rloc = mi * 16 + g + half * 8;
                size_t base = ((size_t)(b0r + rloc) * S_LEN + t) * DIM;
#pragma unroll
                for (int nt = 0; nt < 4; nt++) {
                    int c  = w * 32 + nt * 8 + tig * 2;
                    float v0 = tanhf(acc[mi][nt][half * 2]);
                    float v1 = tanhf(acc[mi][nt][half * 2 + 1]);
                    *reinterpret_cast<float2*>(out + base + c) = make_float2(v0, v1);
                    *reinterpret_cast<float2*>(&hs[rloc * SSTRIDE + c]) = make_float2(v0, v1);
                }
            }
        __syncthreads();   // hs for step t fully written before next step reads it
    }
}

extern "C" void kernel_launch(void* const* d_in, const int* in_sizes, int n_in,
                              void* d_out, int out_size) {
    const float* x  = (const float*)d_in[0];   // [512,512,256]
    const float* Wx = (const float*)d_in[1];   // [512,256,256]
    const float* Wh = (const float*)d_in[2];   // [512,256,256]
    float* out = (float*)d_out;                // [512,512,256]

    dim3 g1(B_SZ / TM, S_LEN);                 // 16 x 512 CTAs
    rnn_k1_xwx<<<g1, 256>>>(x, Wx, out);       // out = Z
    rnn_k2_recur<<<B_SZ / TM, 256>>>(Wh, out); // out = h (in-place over Z)
}

// round 5
// speedup vs baseline: 1.0230x; 1.0230x over previous
#include <cuda_runtime.h>

// RNNBlock: h_t = tanh(x_t @ Wx[t] + h_{t-1} @ Wh[t]),  h_{-1} = 0
// B=512, S=512, D_IN=D_OUT=256, fp32 in/out.
//
// Decomposition:
//   K1 (parallel):  out[b,t,:] = x[b,t,:] @ Wx[t]          (Z stored in d_out)
//   K2 (recurrent): per-CTA batch slice, loop t:
//                   out[b,t,:] = tanh(out[b,t,:] + h @ Wh[t]); h = out[b,t,:]
// No inter-CTA sync anywhere; Z lives in d_out (read-then-overwrite in place).
// Compute: mma.sync m16n8k8 tf32 (fp32 accumulate), inputs cvt.rna.tf32.

#define S_LEN 512
#define B_SZ  512
#define DIM   256
#define TM    32          // batch rows per CTA tile
#define SSTRIDE 260       // smem row stride (== 4 mod 32 -> conflict-free A frags)

__device__ __forceinline__ unsigned f2tf32(float f) {
    unsigned u;
    asm("cvt.rna.tf32.f32 %0, %1;" : "=r"(u) : "f"(f));
    return u;
}

__device__ __forceinline__ void mma_tf32(float c[4],
                                         unsigned a0, unsigned a1, unsigned a2, unsigned a3,
                                         unsigned b0, unsigned b1) {
    asm volatile(
        "mma.sync.aligned.m16n8k8.row.col.f32.tf32.tf32.f32 "
        "{%0,%1,%2,%3}, {%4,%5,%6,%7}, {%8,%9}, {%0,%1,%2,%3};"
        : "+f"(c[0]), "+f"(c[1]), "+f"(c[2]), "+f"(c[3])
        : "r"(a0), "r"(a1), "r"(a2), "r"(a3), "r"(b0), "r"(b1));
}

// acc[2][4][4] += Asm(32 x 256, row stride SSTRIDE) @ Bg(256x256 row-major [k][n])
// warp covers output cols [nbase, nbase+32). B-frags loaded straight from global
// (each element read exactly once per CTA; L2-cached across CTAs).
__device__ __forceinline__ void gemm_tile(const float* __restrict__ Asm,
                                          const float* __restrict__ Bg,
                                          float acc[2][4][4],
                                          int nbase, int g, int tig) {
#pragma unroll 4
    for (int k0 = 0; k0 < DIM; k0 += 8) {
        unsigned a[2][4];
#pragma unroll
        for (int mi = 0; mi < 2; mi++) {
            int r0 = mi * 16 + g;
            a[mi][0] = f2tf32(Asm[r0 * SSTRIDE + k0 + tig]);
            a[mi][1] = f2tf32(Asm[(r0 + 8) * SSTRIDE + k0 + tig]);
            a[mi][2] = f2tf32(Asm[r0 * SSTRIDE + k0 + tig + 4]);
            a[mi][3] = f2tf32(Asm[(r0 + 8) * SSTRIDE + k0 + tig + 4]);
        }
#pragma unroll
        for (int nt = 0; nt < 4; nt++) {
            int n = nbase + nt * 8 + g;
            unsigned b0 = f2tf32(Bg[(k0 + tig) * DIM + n]);
            unsigned b1 = f2tf32(Bg[(k0 + tig + 4) * DIM + n]);
            mma_tf32(acc[0][nt], a[0][0], a[0][1], a[0][2], a[0][3], b0, b1);
            mma_tf32(acc[1][nt], a[1][0], a[1][1], a[1][2], a[1][3], b0, b1);
        }
    }
}

// ---------------- K1: Z = x @ Wx  (fully parallel over (b-tile, t)) ----------------
__global__ void __launch_bounds__(256)
rnn_k1_xwx(const float* __restrict__ x, const float* __restrict__ Wx,
           float* __restrict__ out) {
    __shared__ float xs[TM * SSTRIDE];
    const int bt  = blockIdx.x;          // 0..15  batch tile
    const int t   = blockIdx.y;          // 0..511 timestep
    const int tid = threadIdx.x;
    const int w = tid >> 5, lane = tid & 31, g = lane >> 2, tig = lane & 3;
    const int b0r = bt * TM;

    // stage x tile [32 x 256] into padded smem (float4, fully coalesced)
    for (int i = tid; i < TM * (DIM / 4); i += 256) {
        int r = i >> 6, c4 = i & 63;
        float4 v = *reinterpret_cast<const float4*>(
            x + ((size_t)(b0r + r) * S_LEN + t) * DIM + c4 * 4);
        *reinterpret_cast<float4*>(&xs[r * SSTRIDE + c4 * 4]) = v;
    }
    __syncthreads();

    float acc[2][4][4] = {};
    gemm_tile(xs, Wx + (size_t)t * DIM * DIM, acc, w * 32, g, tig);

#pragma unroll
    for (int mi = 0; mi < 2; mi++)
#pragma unroll
        for (int half = 0; half < 2; half++) {
            int r = b0r + mi * 16 + g + half * 8;
            size_t base = ((size_t)r * S_LEN + t) * DIM;
#pragma unroll
            for (int nt = 0; nt < 4; nt++) {
                int c = w * 32 + nt * 8 + tig * 2;
                *reinterpret_cast<float2*>(out + base + c) =
                    make_float2(acc[mi][nt][half * 2], acc[mi][nt][half * 2 + 1]);
            }
        }
}

// ---------------- K2: recurrence, batch-parallel (16 independent CTAs) -------------
__global__ void __launch_bounds__(256)
rnn_k2_recur(const float* __restrict__ Wh, float* __restrict__ out) {
    __shared__ float hs[TM * SSTRIDE];   // h_{t-1} for this CTA's 32 rows (fp32)
    const int tid = threadIdx.x;
    const int w = tid >> 5, lane = tid & 31, g = lane >> 2, tig = lane & 3;
    const int b0r = blockIdx.x * TM;

    for (int i = tid; i < TM * SSTRIDE; i += 256) hs[i] = 0.0f;   // h_{-1} = 0
    __syncthreads();

    for (int t = 0; t < S_LEN; t++) {
        float acc[2][4][4];
        // acc = Z (already sitting in out)
#pragma unroll
        for (int mi = 0; mi < 2; mi++)
#pragma unroll
            for (int half = 0; half < 2; half++) {
                int r = b0r + mi * 16 + g + half * 8;
                size_t base = ((size_t)r * S_LEN + t) * DIM;
#pragma unroll
                for (int nt = 0; nt < 4; nt++) {
                    int c = w * 32 + nt * 8 + tig * 2;
                    float2 v = *reinterpret_cast<const float2*>(out + base + c);
                    acc[mi][nt][half * 2]     = v.x;
                    acc[mi][nt][half * 2 + 1] = v.y;
                }
            }

        gemm_tile(hs, Wh + (size_t)t * DIM * DIM, acc, w * 32, g, tig);

        __syncthreads();   // everyone done READING hs for step t

#pragma unroll
        for (int mi = 0; mi < 2; mi++)
#pragma unroll
            for (int half = 0; half < 2; half++) {
                int rloc = mi * 16 + g + half * 8;
                size_t base = ((size_t)(b0r + rloc) * S_LEN + t) * DIM;
#pragma unroll
                for (int nt = 0; nt < 4; nt++) {
                    int c  = w * 32 + nt * 8 + tig * 2;
                    float v0 = tanhf(acc[mi][nt][half * 2]);
                    float v1 = tanhf(acc[mi][nt][half * 2 + 1]);
                    *reinterpret_cast<float2*>(out + base + c) = make_float2(v0, v1);
                    *reinterpret_cast<float2*>(&hs[rloc * SSTRIDE + c]) = make_float2(v0, v1);
                }
            }
        __syncthreads();   // hs for step t fully written before next step reads it
    }
}

extern "C" void kernel_launch(void* const* d_in, const int* in_sizes, int n_in,
                              void* d_out, int out_size) {
    const float* x  = (const float*)d_in[0];   // [512,512,256]
    const float* Wx = (const float*)d_in[1];   // [512,256,256]
    const float* Wh = (const float*)d_in[2];   // [512,256,256]
    float* out = (float*)d_out;                // [512,512,256]

    dim3 g1(B_SZ / TM, S_LEN);                 // 16 x 512 CTAs
    rnn_k1_xwx<<<g1, 256>>>(x, Wx, out);       // out = Z
    rnn_k2_recur<<<B_SZ / TM, 256>>>(Wh, out); // out = h (in-place over Z)
}

// round 6
// speedup vs baseline: 2.4844x; 2.4286x over previous
#include <cuda_runtime.h>

// RNNBlock: h_t = tanh(x_t @ Wx[t] + h_{t-1} @ Wh[t]), h_{-1}=0
// B=512, S=512, D=256, fp32.
//
// K0  (x2): pack Wx/Wh -> tf32 in per-thread-linear mma consumption order.
// K1:       out = x @ Wx (fully parallel, 16x512 CTAs, packed B).
// K2:       recurrence, 32 CTAs x 16 batch rows, packed B stream (LDG.128),
//           h kept in smem as tf32, Z double-buffered via cp.async.

#define S_LEN 512
#define B_SZ  512
#define DIM   256
#define TM1   32
#define TM2   16
#define SSTRIDE 260            // mod 32 == 4 -> conflict-free A-frag LDS
#define WT_STRIDE 65536        // u32 per timestep of packed weights (8*8192)

// packed tf32 weights (scratch via __device__ globals; 128MB each)
__device__ unsigned g_WxP[(size_t)S_LEN * WT_STRIDE];
__device__ unsigned g_WhP[(size_t)S_LEN * WT_STRIDE];

__device__ __forceinline__ unsigned f2tf32(float f) {
    unsigned u;
    asm("cvt.rna.tf32.f32 %0, %1;" : "=r"(u) : "f"(f));
    return u;
}

__device__ __forceinline__ void mma_tf32(float c[4],
                                         unsigned a0, unsigned a1, unsigned a2, unsigned a3,
                                         unsigned b0, unsigned b1) {
    asm volatile(
        "mma.sync.aligned.m16n8k8.row.col.f32.tf32.tf32.f32 "
        "{%0,%1,%2,%3}, {%4,%5,%6,%7}, {%8,%9}, {%0,%1,%2,%3};"
        : "+f"(c[0]), "+f"(c[1]), "+f"(c[2]), "+f"(c[3])
        : "r"(a0), "r"(a1), "r"(a2), "r"(a3), "r"(b0), "r"(b1));
}

__device__ __forceinline__ float fast_tanh(float x) {
    x = fminf(fmaxf(x, -15.f), 15.f);
    float e = __expf(2.f * x);
    return __fdividef(e - 1.f, e + 1.f);
}

__device__ __forceinline__ void cp_async16(void* dst_smem, const void* src) {
    unsigned d = (unsigned)__cvta_generic_to_shared(dst_smem);
    asm volatile("cp.async.cg.shared.global [%0], [%1], 16;" :: "r"(d), "l"(src));
}
#define CP_COMMIT() asm volatile("cp.async.commit_group;")
#define CP_WAIT1()  asm volatile("cp.async.wait_group 1;" ::: "memory")

// ---------------- K0: pack W[t] (row-major [k][n]) into per-thread order ----------
// slot layout (u32): t*65536 + w*8192 + kiter*256 + lane*8 + pair*4
// contents: { B[k0+tig][n], B[k0+tig+4][n], B[k0+tig][n+8], B[k0+tig+4][n+8] }
//           with n = w*32 + pair*16 + g, k0 = kiter*8, g=lane>>2, tig=lane&3
__global__ void __launch_bounds__(256)
pack_w(const float* __restrict__ W, unsigned* __restrict__ P) {
    unsigned idx  = blockIdx.x * 256u + threadIdx.x;   // 8,388,608 uint4 slots
    unsigned pair = idx & 1, lane = (idx >> 1) & 31, kiter = (idx >> 6) & 31,
             w    = (idx >> 11) & 7, t = idx >> 14;
    unsigned g = lane >> 2, tig = lane & 3, k0 = kiter * 8;
    const float* Wt = W + (size_t)t * DIM * DIM;
    unsigned n0 = w * 32 + pair * 16 + g;
    uint4 v;
    v.x = f2tf32(Wt[(k0 + tig)     * DIM + n0]);
    v.y = f2tf32(Wt[(k0 + tig + 4) * DIM + n0]);
    v.z = f2tf32(Wt[(k0 + tig)     * DIM + n0 + 8]);
    v.w = f2tf32(Wt[(k0 + tig + 4) * DIM + n0 + 8]);
    reinterpret_cast<uint4*>(P)[idx] = v;
}

// ---------------- shared GEMM core: acc += As(tf32 smem) @ packed-B stream --------
// Bp must already point at (w*8192 + lane*8); advance per-k-iter is +256.
template<int MI>
__device__ __forceinline__ void gemm_packed(const unsigned* __restrict__ As,
                                            const unsigned* __restrict__ Bp,
                                            float acc[MI][4][4], int g, int tig) {
#pragma unroll
    for (int kit = 0; kit < 32; kit++) {
        uint4 p0 = *reinterpret_cast<const uint4*>(Bp + kit * 256);
        uint4 p1 = *reinterpret_cast<const uint4*>(Bp + kit * 256 + 4);
        const int k0 = kit * 8;
        unsigned a[MI][4];
#pragma unroll
        for (int mi = 0; mi < MI; mi++) {
            int r0 = mi * 16 + g;
            a[mi][0] = As[r0 * SSTRIDE + k0 + tig];
            a[mi][1] = As[(r0 + 8) * SSTRIDE + k0 + tig];
            a[mi][2] = As[r0 * SSTRIDE + k0 + tig + 4];
            a[mi][3] = As[(r0 + 8) * SSTRIDE + k0 + tig + 4];
        }
#pragma unroll
        for (int mi = 0; mi < MI; mi++) {
            mma_tf32(acc[mi][0], a[mi][0], a[mi][1], a[mi][2], a[mi][3], p0.x, p0.y);
            mma_tf32(acc[mi][1], a[mi][0], a[mi][1], a[mi][2], a[mi][3], p0.z, p0.w);
            mma_tf32(acc[mi][2], a[mi][0], a[mi][1], a[mi][2], a[mi][3], p1.x, p1.y);
            mma_tf32(acc[mi][3], a[mi][0], a[mi][1], a[mi][2], a[mi][3], p1.z, p1.w);
        }
    }
}

// ---------------- K1: Z = x @ Wx ---------------------------------------------------
__global__ void __launch_bounds__(256)
rnn_k1(const float* __restrict__ x, float* __restrict__ out) {
    __shared__ unsigned xs[TM1 * SSTRIDE];
    const int bt = blockIdx.x, t = blockIdx.y, tid = threadIdx.x;
    const int w = tid >> 5, lane = tid & 31, g = lane >> 2, tig = lane & 3;
    const int b0r = bt * TM1;

    // stage x tile as tf32 (cvt once here, none in the hot loop)
    for (int i = tid; i < TM1 * (DIM / 4); i += 256) {
        int r = i >> 6, c4 = i & 63;
        float4 v = *reinterpret_cast<const float4*>(
            x + ((size_t)(b0r + r) * S_LEN + t) * DIM + c4 * 4);
        uint4 u = make_uint4(f2tf32(v.x), f2tf32(v.y), f2tf32(v.z), f2tf32(v.w));
        *reinterpret_cast<uint4*>(&xs[r * SSTRIDE + c4 * 4]) = u;
    }
    __syncthreads();

    float acc[2][4][4] = {};
    const unsigned* Bp = g_WxP + (size_t)t * WT_STRIDE + w * 8192 + lane * 8;
    gemm_packed<2>(xs, Bp, acc, g, tig);

#pragma unroll
    for (int mi = 0; mi < 2; mi++)
#pragma unroll
        for (int half = 0; half < 2; half++) {
            int r = b0r + mi * 16 + g + half * 8;
            size_t base = ((size_t)r * S_LEN + t) * DIM;
#pragma unroll
            for (int nt = 0; nt < 4; nt++) {
                int c = w * 32 + nt * 8 + tig * 2;
                *reinterpret_cast<float2*>(out + base + c) =
                    make_float2(acc[mi][nt][half * 2], acc[mi][nt][half * 2 + 1]);
            }
        }
}

// ---------------- K2: recurrence, 32 independent CTAs ------------------------------
__global__ void __launch_bounds__(256)
rnn_k2(float* __restrict__ out) {
    extern __shared__ unsigned smemraw[];
    unsigned* hs = smemraw;                                  // TM2*SSTRIDE (tf32 h)
    float*    zs = reinterpret_cast<float*>(smemraw + TM2 * SSTRIDE); // 2 buffers
    const int ZSZ = TM2 * SSTRIDE;

    const int tid = threadIdx.x;
    const int w = tid >> 5, lane = tid & 31, g = lane >> 2, tig = lane & 3;
    const int b0r = blockIdx.x * TM2;

    for (int i = tid; i < TM2 * SSTRIDE; i += 256) hs[i] = 0u;   // tf32(0) == 0

    // prefetch Z(0) into zs buffer 0 (16 rows x 1KB, 16B chunks)
#pragma unroll
    for (int c = 0; c < 4; c++) {
        int chunk = tid + c * 256;                  // 0..1023
        int r = chunk >> 6, c16 = chunk & 63;
        cp_async16(zs + 0 * ZSZ + r * SSTRIDE + c16 * 4,
                   out + ((size_t)(b0r + r) * S_LEN + 0) * DIM + c16 * 4);
    }
    CP_COMMIT();

    const unsigned* BpBase = g_WhP + w * 8192 + lane * 8;

    for (int t = 0; t < S_LEN; t++) {
        const int cb = t & 1, nb = (t + 1) & 1;

        // prefetch Z(t+1)
        if (t + 1 < S_LEN) {
#pragma unroll
            for (int c = 0; c < 4; c++) {
                int chunk = tid + c * 256;
                int r = chunk >> 6, c16 = chunk & 63;
                cp_async16(zs + nb * ZSZ + r * SSTRIDE + c16 * 4,
                           out + ((size_t)(b0r + r) * S_LEN + (t + 1)) * DIM + c16 * 4);
            }
        }
        CP_COMMIT();
        CP_WAIT1();          // Z(t) landed (group t-1 done; group t still in flight)
        __syncthreads();     // Z(t) visible to all; hs(t-1) writes visible to all

        // acc = Z(t)
        float acc[1][4][4];
        const float* Z = zs + cb * ZSZ;
#pragma unroll
        for (int half = 0; half < 2; half++) {
            int rloc = g + half * 8;
#pragma unroll
            for (int nt = 0; nt < 4; nt++) {
                int col = w * 32 + nt * 8 + tig * 2;
                float2 v = *reinterpret_cast<const float2*>(Z + rloc * SSTRIDE + col);
                acc[0][nt][half * 2]     = v.x;
                acc[0][nt][half * 2 + 1] = v.y;
            }
        }

        gemm_packed<1>(hs, BpBase + (size_t)t * WT_STRIDE, acc, g, tig);

        __syncthreads();     // everyone done READING hs for step t

        // epilogue: tanh, write out(t), refresh hs as tf32
#pragma unroll
        for (int half = 0; half < 2; half++) {
            int rloc = g + half * 8;
            size_t base = ((size_t)(b0r + rloc) * S_LEN + t) * DIM;
#pragma unroll
            for (int nt = 0; nt < 4; nt++) {
                int col = w * 32 + nt * 8 + tig * 2;
                float v0 = fast_tanh(acc[0][nt][half * 2]);
                float v1 = fast_tanh(acc[0][nt][half * 2 + 1]);
                *reinterpret_cast<float2*>(out + base + col) = make_float2(v0, v1);
                hs[rloc * SSTRIDE + col]     = f2tf32(v0);
                hs[rloc * SSTRIDE + col + 1] = f2tf32(v1);
            }
        }
    }
}

extern "C" void kernel_launch(void* const* d_in, const int* in_sizes, int n_in,
                              void* d_out, int out_size) {
    const float* x  = (const float*)d_in[0];   // [512,512,256]
    const float* Wx = (const float*)d_in[1];   // [512,256,256]
    const float* Wh = (const float*)d_in[2];   // [512,256,256]
    float* out = (float*)d_out;                // [512,512,256]

    unsigned* wxp; cudaGetSymbolAddress((void**)&wxp, g_WxP);
    unsigned* whp; cudaGetSymbolAddress((void**)&whp, g_WhP);

    static int smem_set = 0;
    const int k2_smem = 3 * TM2 * SSTRIDE * (int)sizeof(unsigned);  // ~49.9KB
    if (!smem_set) {
        cudaFuncSetAttribute(rnn_k2, cudaFuncAttributeMaxDynamicSharedMemorySize, k2_smem);
        smem_set = 1;
    }

    pack_w<<<32768, 256>>>(Wx, wxp);
    pack_w<<<32768, 256>>>(Wh, whp);

    dim3 g1(B_SZ / TM1, S_LEN);                // 16 x 512 CTAs
    rnn_k1<<<g1, 256>>>(x, out);               // out = Z
    rnn_k2<<<B_SZ / TM2, 256, k2_smem>>>(out); // out = h (in-place over Z)
}

// round 7
// speedup vs baseline: 4.5941x; 1.8492x over previous
#include <cuda_runtime.h>

// RNNBlock: h_t = tanh(x_t @ Wx[t] + h_{t-1} @ Wh[t]), h_{-1}=0
// B=512, S=512, D=256, fp32.
//
// K0  (x2): pack Wx/Wh -> tf32 in per-thread-linear mma consumption order.
// K1:       out = x @ Wx (fully parallel, 16x512 CTAs, packed B).
// K2:       recurrence, 32 CTAs x 16 batch rows; weight stream consumed through
//           a depth-8 register prefetch ring (64 regs) that never drains across
//           timesteps; h kept in smem as tf32; Z double-buffered via cp.async.

#define S_LEN 512
#define B_SZ  512
#define DIM   256
#define TM1   32
#define TM2   16
#define SSTRIDE 260            // mod 32 == 4 -> conflict-free A-frag LDS
#define WT_STRIDE 65536        // u32 per timestep of packed weights (8*8192)
#define PFD 8                  // weight prefetch ring depth (kits)

// packed tf32 weights (scratch via __device__ globals; 128MB each)
__device__ unsigned g_WxP[(size_t)S_LEN * WT_STRIDE];
__device__ unsigned g_WhP[(size_t)S_LEN * WT_STRIDE];

__device__ __forceinline__ unsigned f2tf32(float f) {
    unsigned u;
    asm("cvt.rna.tf32.f32 %0, %1;" : "=r"(u) : "f"(f));
    return u;
}

__device__ __forceinline__ void mma_tf32(float c[4],
                                         unsigned a0, unsigned a1, unsigned a2, unsigned a3,
                                         unsigned b0, unsigned b1) {
    asm volatile(
        "mma.sync.aligned.m16n8k8.row.col.f32.tf32.tf32.f32 "
        "{%0,%1,%2,%3}, {%4,%5,%6,%7}, {%8,%9}, {%0,%1,%2,%3};"
        : "+f"(c[0]), "+f"(c[1]), "+f"(c[2]), "+f"(c[3])
        : "r"(a0), "r"(a1), "r"(a2), "r"(a3), "r"(b0), "r"(b1));
}

__device__ __forceinline__ float fast_tanh(float x) {
    x = fminf(fmaxf(x, -15.f), 15.f);
    float e = __expf(2.f * x);
    return __fdividef(e - 1.f, e + 1.f);
}

__device__ __forceinline__ void cp_async16(void* dst_smem, const void* src) {
    unsigned d = (unsigned)__cvta_generic_to_shared(dst_smem);
    asm volatile("cp.async.cg.shared.global [%0], [%1], 16;" :: "r"(d), "l"(src));
}
#define CP_COMMIT() asm volatile("cp.async.commit_group;")
#define CP_WAIT1()  asm volatile("cp.async.wait_group 1;" ::: "memory")

// ---------------- K0: pack W[t] (row-major [k][n]) into per-thread order ----------
// slot layout (u32): t*65536 + w*8192 + kiter*256 + lane*8 + pair*4
// contents: { B[k0+tig][n], B[k0+tig+4][n], B[k0+tig][n+8], B[k0+tig+4][n+8] }
//           with n = w*32 + pair*16 + g, k0 = kiter*8, g=lane>>2, tig=lane&3
__global__ void __launch_bounds__(256)
pack_w(const float* __restrict__ W, unsigned* __restrict__ P) {
    unsigned idx  = blockIdx.x * 256u + threadIdx.x;   // 8,388,608 uint4 slots
    unsigned pair = idx & 1, lane = (idx >> 1) & 31, kiter = (idx >> 6) & 31,
             w    = (idx >> 11) & 7, t = idx >> 14;
    unsigned g = lane >> 2, tig = lane & 3, k0 = kiter * 8;
    const float* Wt = W + (size_t)t * DIM * DIM;
    unsigned n0 = w * 32 + pair * 16 + g;
    uint4 v;
    v.x = f2tf32(Wt[(k0 + tig)     * DIM + n0]);
    v.y = f2tf32(Wt[(k0 + tig + 4) * DIM + n0]);
    v.z = f2tf32(Wt[(k0 + tig)     * DIM + n0 + 8]);
    v.w = f2tf32(Wt[(k0 + tig + 4) * DIM + n0 + 8]);
    reinterpret_cast<uint4*>(P)[idx] = v;
}

// ---------------- GEMM core for K1: acc += As(tf32 smem) @ packed-B stream --------
template<int MI>
__device__ __forceinline__ void gemm_packed(const unsigned* __restrict__ As,
                                            const unsigned* __restrict__ Bp,
                                            float acc[MI][4][4], int g, int tig) {
#pragma unroll
    for (int kit = 0; kit < 32; kit++) {
        uint4 p0 = *reinterpret_cast<const uint4*>(Bp + kit * 256);
        uint4 p1 = *reinterpret_cast<const uint4*>(Bp + kit * 256 + 4);
        const int k0 = kit * 8;
        unsigned a[MI][4];
#pragma unroll
        for (int mi = 0; mi < MI; mi++) {
            int r0 = mi * 16 + g;
            a[mi][0] = As[r0 * SSTRIDE + k0 + tig];
            a[mi][1] = As[(r0 + 8) * SSTRIDE + k0 + tig];
            a[mi][2] = As[r0 * SSTRIDE + k0 + tig + 4];
            a[mi][3] = As[(r0 + 8) * SSTRIDE + k0 + tig + 4];
        }
#pragma unroll
        for (int mi = 0; mi < MI; mi++) {
            mma_tf32(acc[mi][0], a[mi][0], a[mi][1], a[mi][2], a[mi][3], p0.x, p0.y);
            mma_tf32(acc[mi][1], a[mi][0], a[mi][1], a[mi][2], a[mi][3], p0.z, p0.w);
            mma_tf32(acc[mi][2], a[mi][0], a[mi][1], a[mi][2], a[mi][3], p1.x, p1.y);
            mma_tf32(acc[mi][3], a[mi][0], a[mi][1], a[mi][2], a[mi][3], p1.z, p1.w);
        }
    }
}

// ---------------- K1: Z = x @ Wx ---------------------------------------------------
__global__ void __launch_bounds__(256)
rnn_k1(const float* __restrict__ x, float* __restrict__ out) {
    __shared__ unsigned xs[TM1 * SSTRIDE];
    const int bt = blockIdx.x, t = blockIdx.y, tid = threadIdx.x;
    const int w = tid >> 5, lane = tid & 31, g = lane >> 2, tig = lane & 3;
    const int b0r = bt * TM1;

    for (int i = tid; i < TM1 * (DIM / 4); i += 256) {
        int r = i >> 6, c4 = i & 63;
        float4 v = *reinterpret_cast<const float4*>(
            x + ((size_t)(b0r + r) * S_LEN + t) * DIM + c4 * 4);
        uint4 u = make_uint4(f2tf32(v.x), f2tf32(v.y), f2tf32(v.z), f2tf32(v.w));
        *reinterpret_cast<uint4*>(&xs[r * SSTRIDE + c4 * 4]) = u;
    }
    __syncthreads();

    float acc[2][4][4] = {};
    const unsigned* Bp = g_WxP + (size_t)t * WT_STRIDE + w * 8192 + lane * 8;
    gemm_packed<2>(xs, Bp, acc, w * 0 + g, tig);   // nbase folded into packing

#pragma unroll
    for (int mi = 0; mi < 2; mi++)
#pragma unroll
        for (int half = 0; half < 2; half++) {
            int r = b0r + mi * 16 + g + half * 8;
            size_t base = ((size_t)r * S_LEN + t) * DIM;
#pragma unroll
            for (int nt = 0; nt < 4; nt++) {
                int c = w * 32 + nt * 8 + tig * 2;
                *reinterpret_cast<float2*>(out + base + c) =
                    make_float2(acc[mi][nt][half * 2], acc[mi][nt][half * 2 + 1]);
            }
        }
}

// ---------------- K2: recurrence, 32 independent CTAs, pipelined weight ring -------
__global__ void __launch_bounds__(256, 1)
rnn_k2(float* __restrict__ out) {
    extern __shared__ unsigned smemraw[];
    unsigned* hs = smemraw;                                  // TM2*SSTRIDE (tf32 h)
    float*    zs = reinterpret_cast<float*>(smemraw + TM2 * SSTRIDE); // 2 buffers
    const int ZSZ = TM2 * SSTRIDE;

    const int tid = threadIdx.x;
    const int w = tid >> 5, lane = tid & 31, g = lane >> 2, tig = lane & 3;
    const int b0r = blockIdx.x * TM2;

    for (int i = tid; i < TM2 * SSTRIDE; i += 256) hs[i] = 0u;   // tf32(0) == 0

    // prefetch Z(0) into zs buffer 0 (16 rows x 1KB, 16B chunks)
#pragma unroll
    for (int c = 0; c < 4; c++) {
        int chunk = tid + c * 256;
        int r = chunk >> 6, c16 = chunk & 63;
        cp_async16(zs + 0 * ZSZ + r * SSTRIDE + c16 * 4,
                   out + ((size_t)(b0r + r) * S_LEN + 0) * DIM + c16 * 4);
    }
    CP_COMMIT();

    // weight prefetch ring: depth PFD kits, never drains across timesteps
    const unsigned* Bt = g_WhP + w * 8192 + lane * 8;   // advances by WT_STRIDE per t
    uint4 pf[PFD][2];
#pragma unroll
    for (int d = 0; d < PFD; d++) {
        pf[d][0] = *reinterpret_cast<const uint4*>(Bt + d * 256);
        pf[d][1] = *reinterpret_cast<const uint4*>(Bt + d * 256 + 4);
    }

    for (int t = 0; t < S_LEN; t++) {
        const int cb = t & 1, nb = (t + 1) & 1;

        // prefetch Z(t+1)
        if (t + 1 < S_LEN) {
#pragma unroll
            for (int c = 0; c < 4; c++) {
                int chunk = tid + c * 256;
                int r = chunk >> 6, c16 = chunk & 63;
                cp_async16(zs + nb * ZSZ + r * SSTRIDE + c16 * 4,
                           out + ((size_t)(b0r + r) * S_LEN + (t + 1)) * DIM + c16 * 4);
            }
        }
        CP_COMMIT();
        CP_WAIT1();          // Z(t) landed
        __syncthreads();     // Z(t) + hs(t-1) visible to all

        // acc = Z(t)
        float acc[4][4];
        const float* Z = zs + cb * ZSZ;
#pragma unroll
        for (int half = 0; half < 2; half++) {
            int rloc = g + half * 8;
#pragma unroll
            for (int nt = 0; nt < 4; nt++) {
                int col = w * 32 + nt * 8 + tig * 2;
                float2 v = *reinterpret_cast<const float2*>(Z + rloc * SSTRIDE + col);
                acc[nt][half * 2]     = v.x;
                acc[nt][half * 2 + 1] = v.y;
            }
        }

        // GEMM with register-ring weight stream
        const bool notlast = (t + 1 < S_LEN);
#pragma unroll
        for (int kit = 0; kit < 32; kit++) {
            uint4 p0 = pf[kit & (PFD - 1)][0];
            uint4 p1 = pf[kit & (PFD - 1)][1];

            // refill ring slot with kit+PFD (spills into step t+1's weights)
            {
                const int nk = kit + PFD;
                const unsigned* src = (nk < 32)
                    ? (Bt + nk * 256)
                    : (Bt + WT_STRIDE + (nk - 32) * 256);
                if (nk < 32 || notlast) {
                    pf[kit & (PFD - 1)][0] = *reinterpret_cast<const uint4*>(src);
                    pf[kit & (PFD - 1)][1] = *reinterpret_cast<const uint4*>(src + 4);
                }
            }

            const int k0 = kit * 8;
            unsigned a0 = hs[g * SSTRIDE + k0 + tig];
            unsigned a1 = hs[(g + 8) * SSTRIDE + k0 + tig];
            unsigned a2 = hs[g * SSTRIDE + k0 + tig + 4];
            unsigned a3 = hs[(g + 8) * SSTRIDE + k0 + tig + 4];

            mma_tf32(acc[0], a0, a1, a2, a3, p0.x, p0.y);
            mma_tf32(acc[1], a0, a1, a2, a3, p0.z, p0.w);
            mma_tf32(acc[2], a0, a1, a2, a3, p1.x, p1.y);
            mma_tf32(acc[3], a0, a1, a2, a3, p1.z, p1.w);
        }

        __syncthreads();     // everyone done READING hs for step t

        // epilogue: tanh, write out(t), refresh hs as tf32
#pragma unroll
        for (int half = 0; half < 2; half++) {
            int rloc = g + half * 8;
            size_t base = ((size_t)(b0r + rloc) * S_LEN + t) * DIM;
#pragma unroll
            for (int nt = 0; nt < 4; nt++) {
                int col = w * 32 + nt * 8 + tig * 2;
                float v0 = fast_tanh(acc[nt][half * 2]);
                float v1 = fast_tanh(acc[nt][half * 2 + 1]);
                *reinterpret_cast<float2*>(out + base + col) = make_float2(v0, v1);
                hs[rloc * SSTRIDE + col]     = f2tf32(v0);
                hs[rloc * SSTRIDE + col + 1] = f2tf32(v1);
            }
        }

        Bt += WT_STRIDE;
    }
}

extern "C" void kernel_launch(void* const* d_in, const int* in_sizes, int n_in,
                              void* d_out, int out_size) {
    const float* x  = (const float*)d_in[0];   // [512,512,256]
    const float* Wx = (const float*)d_in[1];   // [512,256,256]
    const float* Wh = (const float*)d_in[2];   // [512,256,256]
    float* out = (float*)d_out;                // [512,512,256]

    unsigned* wxp; cudaGetSymbolAddress((void**)&wxp, g_WxP);
    unsigned* whp; cudaGetSymbolAddress((void**)&whp, g_WhP);

    static int smem_set = 0;
    const int k2_smem = 3 * TM2 * SSTRIDE * (int)sizeof(unsigned);  // ~49.9KB
    if (!smem_set) {
        cudaFuncSetAttribute(rnn_k2, cudaFuncAttributeMaxDynamicSharedMemorySize, k2_smem);
        smem_set = 1;
    }

    pack_w<<<32768, 256>>>(Wx, wxp);
    pack_w<<<32768, 256>>>(Wh, whp);

    dim3 g1(B_SZ / TM1, S_LEN);                // 16 x 512 CTAs
    rnn_k1<<<g1, 256>>>(x, out);               // out = Z
    rnn_k2<<<B_SZ / TM2, 256, k2_smem>>>(out); // out = h (in-place over Z)
}

// round 8
// speedup vs baseline: 5.4548x; 1.1874x over previous
#include <cuda_runtime.h>

// RNNBlock: h_t = tanh(x_t @ Wx[t] + h_{t-1} @ Wh[t]), h_{-1}=0
// B=512, S=512, D=256, fp32.
//
// K0a: pack Wx -> tf32, 8-warp consumption order (for K1).
// K0b: pack Wh -> tf32, 16-warp consumption order (for K2).
// K1:  out = x @ Wx (parallel, 16x512 CTAs).
// K2:  recurrence, 32 CTAs x 16 rows x 512 threads (16 warps, 16 cols each);
//      weights via depth-8 register ring (1 LDG.128/kit/warp);
//      h kept in smem in mma-A register order -> 1 LDS.128/kit/warp;
//      Z double-buffered via cp.async.

#define S_LEN 512
#define B_SZ  512
#define DIM   256
#define TM1   32
#define TM2   16
#define SSTRIDE 260            // zs row stride
#define WT_STRIDE 65536        // u32 per timestep of packed weights
#define PFD 8                  // weight prefetch ring depth (kits)

__device__ unsigned g_WxP[(size_t)S_LEN * WT_STRIDE];
__device__ unsigned g_WhP[(size_t)S_LEN * WT_STRIDE];

__device__ __forceinline__ unsigned f2tf32(float f) {
    unsigned u;
    asm("cvt.rna.tf32.f32 %0, %1;" : "=r"(u) : "f"(f));
    return u;
}

__device__ __forceinline__ void mma_tf32(float c[4],
                                         unsigned a0, unsigned a1, unsigned a2, unsigned a3,
                                         unsigned b0, unsigned b1) {
    asm volatile(
        "mma.sync.aligned.m16n8k8.row.col.f32.tf32.tf32.f32 "
        "{%0,%1,%2,%3}, {%4,%5,%6,%7}, {%8,%9}, {%0,%1,%2,%3};"
        : "+f"(c[0]), "+f"(c[1]), "+f"(c[2]), "+f"(c[3])
        : "r"(a0), "r"(a1), "r"(a2), "r"(a3), "r"(b0), "r"(b1));
}

__device__ __forceinline__ float fast_tanh(float x) {
    x = fminf(fmaxf(x, -15.f), 15.f);
    float e = __expf(2.f * x);
    return __fdividef(e - 1.f, e + 1.f);
}

__device__ __forceinline__ void cp_async16(void* dst_smem, const void* src) {
    unsigned d = (unsigned)__cvta_generic_to_shared(dst_smem);
    asm volatile("cp.async.cg.shared.global [%0], [%1], 16;" :: "r"(d), "l"(src));
}
#define CP_COMMIT() asm volatile("cp.async.commit_group;")
#define CP_WAIT1()  asm volatile("cp.async.wait_group 1;" ::: "memory")

// ---------- K0a: pack Wx for K1 (8-warp layout, unchanged from R6) ----------------
// slot (u32): t*65536 + w*8192 + kit*256 + lane*8 + pair*4
__global__ void __launch_bounds__(256)
pack_wx(const float* __restrict__ W, unsigned* __restrict__ P) {
    unsigned idx  = blockIdx.x * 256u + threadIdx.x;
    unsigned pair = idx & 1, lane = (idx >> 1) & 31, kit = (idx >> 6) & 31,
             w    = (idx >> 11) & 7, t = idx >> 14;
    unsigned g = lane >> 2, tig = lane & 3, k0 = kit * 8;
    const float* Wt = W + (size_t)t * DIM * DIM;
    unsigned n0 = w * 32 + pair * 16 + g;
    uint4 v;
    v.x = f2tf32(Wt[(k0 + tig)     * DIM + n0]);
    v.y = f2tf32(Wt[(k0 + tig + 4) * DIM + n0]);
    v.z = f2tf32(Wt[(k0 + tig)     * DIM + n0 + 8]);
    v.w = f2tf32(Wt[(k0 + tig + 4) * DIM + n0 + 8]);
    reinterpret_cast<uint4*>(P)[idx] = v;
}

// ---------- K0b: pack Wh for K2 (16-warp layout) ----------------------------------
// uint4 slot index: t*16384 + w*1024 + kit*32 + lane
// contents for warp w (cols 16w..16w+16), lane (g,tig), k0=kit*8:
//   { W[k0+tig][n0], W[k0+tig+4][n0], W[k0+tig][n0+8], W[k0+tig+4][n0+8] }, n0=16w+g
__global__ void __launch_bounds__(256)
pack_wh(const float* __restrict__ W, unsigned* __restrict__ P) {
    unsigned idx  = blockIdx.x * 256u + threadIdx.x;   // uint4 slots
    unsigned lane = idx & 31, kit = (idx >> 5) & 31,
             w    = (idx >> 10) & 15, t = idx >> 14;
    unsigned g = lane >> 2, tig = lane & 3, k0 = kit * 8;
    const float* Wt = W + (size_t)t * DIM * DIM;
    unsigned n0 = w * 16 + g;
    uint4 v;
    v.x = f2tf32(Wt[(k0 + tig)     * DIM + n0]);
    v.y = f2tf32(Wt[(k0 + tig + 4) * DIM + n0]);
    v.z = f2tf32(Wt[(k0 + tig)     * DIM + n0 + 8]);
    v.w = f2tf32(Wt[(k0 + tig + 4) * DIM + n0 + 8]);
    reinterpret_cast<uint4*>(P)[idx] = v;
}

// ---------- K1: Z = x @ Wx (8-warp gemm, as before) -------------------------------
__global__ void __launch_bounds__(256)
rnn_k1(const float* __restrict__ x, float* __restrict__ out) {
    __shared__ unsigned xs[TM1 * SSTRIDE];
    const int bt = blockIdx.x, t = blockIdx.y, tid = threadIdx.x;
    const int w = tid >> 5, lane = tid & 31, g = lane >> 2, tig = lane & 3;
    const int b0r = bt * TM1;

    for (int i = tid; i < TM1 * (DIM / 4); i += 256) {
        int r = i >> 6, c4 = i & 63;
        float4 v = *reinterpret_cast<const float4*>(
            x + ((size_t)(b0r + r) * S_LEN + t) * DIM + c4 * 4);
        uint4 u = make_uint4(f2tf32(v.x), f2tf32(v.y), f2tf32(v.z), f2tf32(v.w));
        *reinterpret_cast<uint4*>(&xs[r * SSTRIDE + c4 * 4]) = u;
    }
    __syncthreads();

    float acc[2][4][4] = {};
    const unsigned* Bp = g_WxP + (size_t)t * WT_STRIDE + w * 8192 + lane * 8;
#pragma unroll
    for (int kit = 0; kit < 32; kit++) {
        uint4 p0 = *reinterpret_cast<const uint4*>(Bp + kit * 256);
        uint4 p1 = *reinterpret_cast<const uint4*>(Bp + kit * 256 + 4);
        const int k0 = kit * 8;
        unsigned a[2][4];
#pragma unroll
        for (int mi = 0; mi < 2; mi++) {
            int r0 = mi * 16 + g;
            a[mi][0] = xs[r0 * SSTRIDE + k0 + tig];
            a[mi][1] = xs[(r0 + 8) * SSTRIDE + k0 + tig];
            a[mi][2] = xs[r0 * SSTRIDE + k0 + tig + 4];
            a[mi][3] = xs[(r0 + 8) * SSTRIDE + k0 + tig + 4];
        }
#pragma unroll
        for (int mi = 0; mi < 2; mi++) {
            mma_tf32(acc[mi][0], a[mi][0], a[mi][1], a[mi][2], a[mi][3], p0.x, p0.y);
            mma_tf32(acc[mi][1], a[mi][0], a[mi][1], a[mi][2], a[mi][3], p0.z, p0.w);
            mma_tf32(acc[mi][2], a[mi][0], a[mi][1], a[mi][2], a[mi][3], p1.x, p1.y);
            mma_tf32(acc[mi][3], a[mi][0], a[mi][1], a[mi][2], a[mi][3], p1.z, p1.w);
        }
    }

#pragma unroll
    for (int mi = 0; mi < 2; mi++)
#pragma unroll
        for (int half = 0; half < 2; half++) {
            int r = b0r + mi * 16 + g + half * 8;
            size_t base = ((size_t)r * S_LEN + t) * DIM;
#pragma unroll
            for (int nt = 0; nt < 4; nt++) {
                int c = w * 32 + nt * 8 + tig * 2;
                *reinterpret_cast<float2*>(out + base + c) =
                    make_float2(acc[mi][nt][half * 2], acc[mi][nt][half * 2 + 1]);
            }
        }
}

// ---------- K2: recurrence, 32 CTAs x 512 threads ---------------------------------
// apack smem layout (u32): kit*128 + lane*4 + j, holding the m16k8 A-frag for kit
// in mma register order: j0=A[g][k0+tig], j1=A[g+8][k0+tig],
//                        j2=A[g][k0+tig+4], j3=A[g+8][k0+tig+4]   (lane=(g<<2)|tig)
__global__ void __launch_bounds__(512, 1)
rnn_k2(float* __restrict__ out) {
    extern __shared__ unsigned smemraw[];
    unsigned* apack = smemraw;                                // 32*128 = 4096 u32
    float*    zs    = reinterpret_cast<float*>(smemraw + 4096);
    const int ZSZ = TM2 * SSTRIDE;

    const int tid = threadIdx.x;
    const int w = tid >> 5, lane = tid & 31, g = lane >> 2, tig = lane & 3;
    const int b0r = blockIdx.x * TM2;

    for (int i = tid; i < 4096; i += 512) apack[i] = 0u;      // h_{-1}=0 (tf32 0 == 0)

    // prefetch Z(0): 16 rows x 1KB = 1024 chunks of 16B, 512 threads -> 2 each
#pragma unroll
    for (int c = 0; c < 2; c++) {
        int chunk = tid + c * 512;
        int r = chunk >> 6, c16 = chunk & 63;
        cp_async16(zs + 0 * ZSZ + r * SSTRIDE + c16 * 4,
                   out + ((size_t)(b0r + r) * S_LEN + 0) * DIM + c16 * 4);
    }
    CP_COMMIT();

    // weight ring: 1 uint4 per kit, depth PFD
    const unsigned* Bt = g_WhP + w * 4096 + lane * 4;   // +WT_STRIDE per t
    uint4 pf[PFD];
#pragma unroll
    for (int d = 0; d < PFD; d++)
        pf[d] = *reinterpret_cast<const uint4*>(Bt + d * 128);

    for (int t = 0; t < S_LEN; t++) {
        const int cb = t & 1, nb = (t + 1) & 1;
        const bool notlast = (t + 1 < S_LEN);

        if (notlast) {
#pragma unroll
            for (int c = 0; c < 2; c++) {
                int chunk = tid + c * 512;
                int r = chunk >> 6, c16 = chunk & 63;
                cp_async16(zs + nb * ZSZ + r * SSTRIDE + c16 * 4,
                           out + ((size_t)(b0r + r) * S_LEN + (t + 1)) * DIM + c16 * 4);
            }
        }
        CP_COMMIT();
        CP_WAIT1();          // Z(t) landed
        __syncthreads();     // Z(t) + apack(t-1 epilogue) visible to all

        // acc = Z(t): warp covers cols [16w, 16w+16)
        float acc[2][4];
        const float* Z = zs + cb * ZSZ;
#pragma unroll
        for (int half = 0; half < 2; half++) {
            int rloc = g + half * 8;
#pragma unroll
            for (int nt = 0; nt < 2; nt++) {
                int col = w * 16 + nt * 8 + tig * 2;
                float2 v = *reinterpret_cast<const float2*>(Z + rloc * SSTRIDE + col);
                acc[nt][half * 2]     = v.x;
                acc[nt][half * 2 + 1] = v.y;
            }
        }

        // GEMM: 32 kits, 1 LDG.128 (ring) + 1 LDS.128 + 2 MMA per kit
#pragma unroll
        for (int kit = 0; kit < 32; kit++) {
            uint4 p = pf[kit & (PFD - 1)];
            {
                const int nk = kit + PFD;
                const unsigned* src = (nk < 32)
                    ? (Bt + nk * 128)
                    : (Bt + WT_STRIDE + (nk - 32) * 128);
                if (nk < 32 || notlast)
                    pf[kit & (PFD - 1)] = *reinterpret_cast<const uint4*>(src);
            }
            uint4 a = *reinterpret_cast<const uint4*>(&apack[kit * 128 + lane * 4]);
            mma_tf32(acc[0], a.x, a.y, a.z, a.w, p.x, p.y);
            mma_tf32(acc[1], a.x, a.y, a.z, a.w, p.z, p.w);
        }

        __syncthreads();     // all reads of apack(t) done before epilogue rewrites

        // epilogue: tanh -> out(t) + apack in register order for step t+1
#pragma unroll
        for (int half = 0; half < 2; half++) {
            int rloc = g + half * 8;
            size_t base = ((size_t)(b0r + rloc) * S_LEN + t) * DIM;
#pragma unroll
            for (int nt = 0; nt < 2; nt++) {
                int col = w * 16 + nt * 8 + tig * 2;
                float v0 = fast_tanh(acc[nt][half * 2]);
                float v1 = fast_tanh(acc[nt][half * 2 + 1]);
                *reinterpret_cast<float2*>(out + base + col) = make_float2(v0, v1);
                // scatter into apack: value h[rloc][c], c = col + e
                const int kit = 2 * w + nt;
#pragma unroll
                for (int e = 0; e < 2; e++) {
                    int co = tig * 2 + e;                  // c & 7
                    int lp = g * 4 + (co & 3);
                    int j  = (co >= 4 ? 2 : 0) + half;
                    apack[kit * 128 + lp * 4 + j] = f2tf32(e ? v1 : v0);
                }
            }
        }

        Bt += WT_STRIDE;
    }
}

extern "C" void kernel_launch(void* const* d_in, const int* in_sizes, int n_in,
                              void* d_out, int out_size) {
    const float* x  = (const float*)d_in[0];   // [512,512,256]
    const float* Wx = (const float*)d_in[1];   // [512,256,256]
    const float* Wh = (const float*)d_in[2];   // [512,256,256]
    float* out = (float*)d_out;                // [512,512,256]

    unsigned* wxp; cudaGetSymbolAddress((void**)&wxp, g_WxP);
    unsigned* whp; cudaGetSymbolAddress((void**)&whp, g_WhP);

    static int smem_set = 0;
    const int k2_smem = (4096 + 2 * TM2 * SSTRIDE) * (int)sizeof(unsigned);  // ~49.7KB
    if (!smem_set) {
        cudaFuncSetAttribute(rnn_k2, cudaFuncAttributeMaxDynamicSharedMemorySize, k2_smem);
        smem_set = 1;
    }

    pack_wx<<<32768, 256>>>(Wx, wxp);
    pack_wh<<<32768, 256>>>(Wh, whp);

    dim3 g1(B_SZ / TM1, S_LEN);                // 16 x 512 CTAs
    rnn_k1<<<g1, 256>>>(x, out);               // out = Z
    rnn_k2<<<B_SZ / TM2, 512, k2_smem>>>(out); // out = h (in-place over Z)
}